// round 2
// baseline (speedup 1.0000x reference)
#include <cuda_runtime.h>
#include <math.h>

#define BB 8
#define NN 2048
#define CC 768
#define HH 12
#define DD 64
#define F3 (3*CC)   // 2304

// Scratch (static device allocations are the sanctioned no-alloc path)
__device__ float g_qkv[(size_t)BB*NN*F3];   // [B,N,3C]  ~151 MB
__device__ float g_attn[(size_t)BB*NN*CC];  // [B,N,C]   ~50 MB

// ---------------------------------------------------------------------------
// SGEMM:  C[m,n] = sum_k A[m,k]*B[n,k] (+ bias[n])
// A: [M,K] row-major, B: [N,K] row-major (both K-contiguous).
// 128x128 block tile, BK=16, 256 threads, 8x8 per-thread microtile.
// M,N multiples of 128; K multiple of 16 (true for all our shapes).
// ---------------------------------------------------------------------------
__global__ __launch_bounds__(256)
void sgemm_nt(const float* __restrict__ A, const float* __restrict__ B,
              const float* __restrict__ bias, float* __restrict__ C,
              int M, int N, int K)
{
    __shared__ float As[16][132];   // [k][m], padded to dodge store conflicts
    __shared__ float Bs[16][132];   // [k][n]

    const int t  = threadIdx.x;
    const int m0 = blockIdx.y * 128;
    const int n0 = blockIdx.x * 128;
    const int ty = t >> 4;          // 0..15
    const int tx = t & 15;          // 0..15

    float acc[8][8];
    #pragma unroll
    for (int i = 0; i < 8; i++)
        #pragma unroll
        for (int j = 0; j < 8; j++) acc[i][j] = 0.f;

    for (int k0 = 0; k0 < K; k0 += 16) {
        // Load 128x16 tiles of A and B (512 float4 each; 2 per thread)
        #pragma unroll
        for (int r = 0; r < 2; r++) {
            int idx = t + r * 256;        // 0..511
            int row = idx >> 2;           // 0..127
            int c4  = idx & 3;            // which float4 within the 16-wide row
            float4 va = *(const float4*)(A + (size_t)(m0 + row) * K + k0 + c4 * 4);
            As[c4*4+0][row] = va.x; As[c4*4+1][row] = va.y;
            As[c4*4+2][row] = va.z; As[c4*4+3][row] = va.w;
            float4 vb = *(const float4*)(B + (size_t)(n0 + row) * K + k0 + c4 * 4);
            Bs[c4*4+0][row] = vb.x; Bs[c4*4+1][row] = vb.y;
            Bs[c4*4+2][row] = vb.z; Bs[c4*4+3][row] = vb.w;
        }
        __syncthreads();

        #pragma unroll
        for (int kk = 0; kk < 16; kk++) {
            float a[8], b[8];
            #pragma unroll
            for (int i = 0; i < 8; i++) a[i] = As[kk][ty * 8 + i];
            #pragma unroll
            for (int j = 0; j < 8; j++) b[j] = Bs[kk][tx * 8 + j];
            #pragma unroll
            for (int i = 0; i < 8; i++)
                #pragma unroll
                for (int j = 0; j < 8; j++)
                    acc[i][j] += a[i] * b[j];
        }
        __syncthreads();
    }

    float bv[8];
    #pragma unroll
    for (int j = 0; j < 8; j++) bv[j] = bias ? bias[n0 + tx * 8 + j] : 0.f;

    #pragma unroll
    for (int i = 0; i < 8; i++) {
        float* cp = C + (size_t)(m0 + ty * 8 + i) * N + n0 + tx * 8;
        float4 v0, v1;
        v0.x = acc[i][0] + bv[0]; v0.y = acc[i][1] + bv[1];
        v0.z = acc[i][2] + bv[2]; v0.w = acc[i][3] + bv[3];
        v1.x = acc[i][4] + bv[4]; v1.y = acc[i][5] + bv[5];
        v1.z = acc[i][6] + bv[6]; v1.w = acc[i][7] + bv[7];
        *(float4*)(cp + 0) = v0;
        *(float4*)(cp + 4) = v1;
    }
}

// ---------------------------------------------------------------------------
// Attention: block = (q-tile of 128 rows, head h, batch b); 1 thread = 1 query
// row; online softmax with lazy max-rescale; K/V streamed in 64-row SMEM tiles.
// qkv layout: g_qkv[b,n, t*768 + h*64 + d], t in {0:q, 1:k, 2:v}
// output: g_attn[b,n, h*64 + d]   (i.e., [B,N,H,D] flattened to [B,N,C])
// ---------------------------------------------------------------------------
__global__ __launch_bounds__(128)
void attn_kernel()
{
    __shared__ float Ks[64][64];
    __shared__ float Vs[64][64];

    const int b = blockIdx.z;
    const int h = blockIdx.y;
    const int n = blockIdx.x * 128 + threadIdx.x;

    const float* qp = g_qkv + ((size_t)(b * NN + n)) * F3 + h * DD;
    float q[64];
    #pragma unroll
    for (int d4 = 0; d4 < 16; d4++) {
        float4 v = *(const float4*)(qp + d4 * 4);
        q[d4*4+0] = v.x; q[d4*4+1] = v.y; q[d4*4+2] = v.z; q[d4*4+3] = v.w;
    }

    float o[64];
    #pragma unroll
    for (int d = 0; d < 64; d++) o[d] = 0.f;
    float m = -INFINITY, l = 0.f;
    const float scale = 0.125f;   // D^-0.5, D=64

    for (int kt = 0; kt < NN / 64; kt++) {
        __syncthreads();   // protect previous tile's reads
        // cooperative load of 64x64 K and V tiles (1024 float4 each / 128 thr)
        #pragma unroll
        for (int r = 0; r < 8; r++) {
            int idx = r * 128 + threadIdx.x;   // 0..1023
            int row = idx >> 4;                // 0..63
            int c4  = idx & 15;                // 0..15
            const float* kp = g_qkv + ((size_t)(b * NN + kt * 64 + row)) * F3
                              + CC + h * DD + c4 * 4;
            *(float4*)&Ks[row][c4 * 4] = *(const float4*)kp;
            *(float4*)&Vs[row][c4 * 4] = *(const float4*)(kp + CC);
        }
        __syncthreads();

        for (int j = 0; j < 64; j++) {
            float s0 = 0.f, s1 = 0.f, s2 = 0.f, s3 = 0.f;
            #pragma unroll
            for (int d4 = 0; d4 < 16; d4++) {
                float4 kv = *(const float4*)&Ks[j][d4 * 4];
                s0 += q[d4*4+0] * kv.x;
                s1 += q[d4*4+1] * kv.y;
                s2 += q[d4*4+2] * kv.z;
                s3 += q[d4*4+3] * kv.w;
            }
            float s = (s0 + s1 + s2 + s3) * scale;
            float p;
            if (s > m) {                         // rare after warmup (~ln N times)
                float corr = __expf(m - s);      // 0 when m == -inf
                l *= corr;
                #pragma unroll
                for (int d = 0; d < 64; d++) o[d] *= corr;
                m = s;
                p = 1.f;
            } else {
                p = __expf(s - m);
            }
            l += p;
            #pragma unroll
            for (int d4 = 0; d4 < 16; d4++) {
                float4 vv = *(const float4*)&Vs[j][d4 * 4];
                o[d4*4+0] += p * vv.x;
                o[d4*4+1] += p * vv.y;
                o[d4*4+2] += p * vv.z;
                o[d4*4+3] += p * vv.w;
            }
        }
    }

    const float inv = 1.f / l;
    float* op = g_attn + ((size_t)(b * NN + n)) * CC + h * DD;
    #pragma unroll
    for (int d4 = 0; d4 < 16; d4++) {
        float4 v;
        v.x = o[d4*4+0] * inv; v.y = o[d4*4+1] * inv;
        v.z = o[d4*4+2] * inv; v.w = o[d4*4+3] * inv;
        *(float4*)(op + d4 * 4) = v;
    }
}

// ---------------------------------------------------------------------------
extern "C" void kernel_launch(void* const* d_in, const int* in_sizes, int n_in,
                              void* d_out, int out_size)
{
    const float* x      = (const float*)d_in[0];
    const float* w_qkv  = (const float*)d_in[1];
    const float* w_proj = (const float*)d_in[2];
    const float* b_proj = (const float*)d_in[3];
    float* out = (float*)d_out;

    float *qkv_ptr, *attn_ptr;
    cudaGetSymbolAddress((void**)&qkv_ptr,  g_qkv);
    cudaGetSymbolAddress((void**)&attn_ptr, g_attn);

    const int M = BB * NN;   // 16384

    // 1) QKV GEMM: [16384,768] x [2304,768]^T -> [16384,2304]
    {
        dim3 grid(F3 / 128, M / 128);
        sgemm_nt<<<grid, 256>>>(x, w_qkv, nullptr, qkv_ptr, M, F3, CC);
    }

    // 2) Attention
    {
        dim3 grid(NN / 128, HH, BB);
        attn_kernel<<<grid, 128>>>();
    }

    // 3) Proj GEMM + bias: [16384,768] x [768,768]^T -> [16384,768]
    {
        dim3 grid(CC / 128, M / 128);
        sgemm_nt<<<grid, 256>>>(attn_ptr, w_proj, b_proj, out, M, CC, CC);
    }
}

// round 4
// speedup vs baseline: 2.1399x; 2.1399x over previous
#include <cuda_runtime.h>
#include <cuda_bf16.h>
#include <math.h>

#define BB 8
#define NN 2048
#define CC 768
#define HH 12
#define DD 64
#define F3 (3*CC)   // 2304
#define QT 64       // query rows per block
#define KT 64       // keys per tile

// Scratch (static device allocations are the sanctioned no-alloc path)
__device__ float g_qkv[(size_t)BB*NN*F3];   // [B,N,3C]  ~151 MB
__device__ float g_attn[(size_t)BB*NN*CC];  // [B,N,C]   ~50 MB

// ---------------------------------------------------------------------------
// helpers
// ---------------------------------------------------------------------------
__device__ __forceinline__ float tf32r(float x) {
    unsigned u;
    asm("cvt.rna.tf32.f32 %0, %1;" : "=r"(u) : "f"(x));
    return __uint_as_float(u);
}

__device__ __forceinline__ unsigned bf16pack(float lo, float hi) {
    __nv_bfloat162 t = __floats2bfloat162_rn(lo, hi);   // x = lo (low 16b), y = hi
    return *(unsigned*)&t;
}

// D += A(16x8 tf32) * B(8x8 tf32), fp32 accum
__device__ __forceinline__ void mma_tf32(float* c, const unsigned* a,
                                         unsigned b0, unsigned b1) {
    asm volatile(
        "mma.sync.aligned.m16n8k8.row.col.f32.tf32.tf32.f32 "
        "{%0,%1,%2,%3}, {%4,%5,%6,%7}, {%8,%9}, {%0,%1,%2,%3};"
        : "+f"(c[0]), "+f"(c[1]), "+f"(c[2]), "+f"(c[3])
        : "r"(a[0]), "r"(a[1]), "r"(a[2]), "r"(a[3]), "r"(b0), "r"(b1));
}

// D += A(16x16 bf16) * B(16x8 bf16), fp32 accum
__device__ __forceinline__ void mma_bf16(float* c, unsigned a0, unsigned a1,
                                         unsigned a2, unsigned a3,
                                         unsigned b0, unsigned b1) {
    asm volatile(
        "mma.sync.aligned.m16n8k16.row.col.f32.bf16.bf16.f32 "
        "{%0,%1,%2,%3}, {%4,%5,%6,%7}, {%8,%9}, {%0,%1,%2,%3};"
        : "+f"(c[0]), "+f"(c[1]), "+f"(c[2]), "+f"(c[3])
        : "r"(a0), "r"(a1), "r"(a2), "r"(a3), "r"(b0), "r"(b1));
}

// ---------------------------------------------------------------------------
// SGEMM:  C[m,n] = sum_k A[m,k]*B[n,k] (+ bias[n])   (unchanged, fp32-exact)
// ---------------------------------------------------------------------------
__global__ __launch_bounds__(256)
void sgemm_nt(const float* __restrict__ A, const float* __restrict__ B,
              const float* __restrict__ bias, float* __restrict__ C,
              int M, int N, int K)
{
    __shared__ float As[16][132];
    __shared__ float Bs[16][132];

    const int t  = threadIdx.x;
    const int m0 = blockIdx.y * 128;
    const int n0 = blockIdx.x * 128;
    const int ty = t >> 4;
    const int tx = t & 15;

    float acc[8][8];
    #pragma unroll
    for (int i = 0; i < 8; i++)
        #pragma unroll
        for (int j = 0; j < 8; j++) acc[i][j] = 0.f;

    for (int k0 = 0; k0 < K; k0 += 16) {
        #pragma unroll
        for (int r = 0; r < 2; r++) {
            int idx = t + r * 256;
            int row = idx >> 2;
            int c4  = idx & 3;
            float4 va = *(const float4*)(A + (size_t)(m0 + row) * K + k0 + c4 * 4);
            As[c4*4+0][row] = va.x; As[c4*4+1][row] = va.y;
            As[c4*4+2][row] = va.z; As[c4*4+3][row] = va.w;
            float4 vb = *(const float4*)(B + (size_t)(n0 + row) * K + k0 + c4 * 4);
            Bs[c4*4+0][row] = vb.x; Bs[c4*4+1][row] = vb.y;
            Bs[c4*4+2][row] = vb.z; Bs[c4*4+3][row] = vb.w;
        }
        __syncthreads();

        #pragma unroll
        for (int kk = 0; kk < 16; kk++) {
            float a[8], b[8];
            #pragma unroll
            for (int i = 0; i < 8; i++) a[i] = As[kk][ty * 8 + i];
            #pragma unroll
            for (int j = 0; j < 8; j++) b[j] = Bs[kk][tx * 8 + j];
            #pragma unroll
            for (int i = 0; i < 8; i++)
                #pragma unroll
                for (int j = 0; j < 8; j++)
                    acc[i][j] += a[i] * b[j];
        }
        __syncthreads();
    }

    float bv[8];
    #pragma unroll
    for (int j = 0; j < 8; j++) bv[j] = bias ? bias[n0 + tx * 8 + j] : 0.f;

    #pragma unroll
    for (int i = 0; i < 8; i++) {
        float* cp = C + (size_t)(m0 + ty * 8 + i) * N + n0 + tx * 8;
        float4 v0, v1;
        v0.x = acc[i][0] + bv[0]; v0.y = acc[i][1] + bv[1];
        v0.z = acc[i][2] + bv[2]; v0.w = acc[i][3] + bv[3];
        v1.x = acc[i][4] + bv[4]; v1.y = acc[i][5] + bv[5];
        v1.z = acc[i][6] + bv[6]; v1.w = acc[i][7] + bv[7];
        *(float4*)(cp + 0) = v0;
        *(float4*)(cp + 4) = v1;
    }
}

// ---------------------------------------------------------------------------
// Flash attention on tensor cores.
// Block = (64 q-rows, head h, batch b), 128 threads (4 warps).
// Warp w owns S/O strip of rows [16w, 16w+16).
// QK^T: tf32 mma m16n8k8 (scale folded into Q).  P*V: bf16 mma m16n8k16.
// SMEM: Qs/Ks fp32 (tf32-rounded), row stride 68 -> conflict-free B frags.
//       Vt = V transposed to [d][key] bf16, row stride 72 -> conflict-free,
//       key-pairs load as single 32-bit words matching bf16 B fragments.
// ---------------------------------------------------------------------------
__global__ __launch_bounds__(128)
void attn_mma_kernel()
{
    __shared__ float Qs[QT][68];
    __shared__ float Ks[KT][68];
    __shared__ __nv_bfloat16 Vt[DD][72];

    const int b  = blockIdx.z;
    const int h  = blockIdx.y;
    const int n0 = blockIdx.x * QT;
    const int tid  = threadIdx.x;
    const int w    = tid >> 5;
    const int lane = tid & 31;
    const int gid  = lane >> 2;   // 0..7
    const int qq   = lane & 3;    // 0..3

    const size_t base_bn = (size_t)(b * NN) * F3;

    // ---- load Q tile (scaled by D^-0.5, tf32-rounded) ----
    #pragma unroll
    for (int r = 0; r < 8; r++) {
        int idx = r * 128 + tid;        // 0..1023 float4s
        int row = idx >> 4;
        int c4  = idx & 15;
        const float* gp = g_qkv + base_bn + (size_t)(n0 + row) * F3 + h * DD + c4 * 4;
        float4 v = *(const float4*)gp;
        Qs[row][c4*4+0] = tf32r(v.x * 0.125f);
        Qs[row][c4*4+1] = tf32r(v.y * 0.125f);
        Qs[row][c4*4+2] = tf32r(v.z * 0.125f);
        Qs[row][c4*4+3] = tf32r(v.w * 0.125f);
    }
    __syncthreads();

    // ---- Q A-fragments (kept in registers for whole kernel) ----
    unsigned qa[8][4];
    #pragma unroll
    for (int ks = 0; ks < 8; ks++) {
        qa[ks][0] = __float_as_uint(Qs[16*w + gid    ][8*ks + qq    ]);
        qa[ks][1] = __float_as_uint(Qs[16*w + gid + 8][8*ks + qq    ]);
        qa[ks][2] = __float_as_uint(Qs[16*w + gid    ][8*ks + qq + 4]);
        qa[ks][3] = __float_as_uint(Qs[16*w + gid + 8][8*ks + qq + 4]);
    }

    float o[8][4];
    #pragma unroll
    for (int t = 0; t < 8; t++)
        #pragma unroll
        for (int j = 0; j < 4; j++) o[t][j] = 0.f;
    float m0 = -1e30f, m1 = -1e30f, l0 = 0.f, l1 = 0.f;

    for (int kt = 0; kt < NN / KT; kt++) {
        __syncthreads();   // previous tile fully consumed
        // ---- load K tile (tf32) and V tile (transposed bf16) ----
        #pragma unroll
        for (int r = 0; r < 8; r++) {
            int idx = r * 128 + tid;
            int row = idx >> 4;
            int c4  = idx & 15;
            const float* kp = g_qkv + base_bn + (size_t)(kt * KT + row) * F3
                              + CC + h * DD + c4 * 4;
            float4 kv = *(const float4*)kp;
            Ks[row][c4*4+0] = tf32r(kv.x);
            Ks[row][c4*4+1] = tf32r(kv.y);
            Ks[row][c4*4+2] = tf32r(kv.z);
            Ks[row][c4*4+3] = tf32r(kv.w);
            float4 vv = *(const float4*)(kp + CC);
            Vt[c4*4+0][row] = __float2bfloat16_rn(vv.x);
            Vt[c4*4+1][row] = __float2bfloat16_rn(vv.y);
            Vt[c4*4+2][row] = __float2bfloat16_rn(vv.z);
            Vt[c4*4+3][row] = __float2bfloat16_rn(vv.w);
        }
        __syncthreads();

        // ---- S = Q * K^T  (warp strip 16x64) ----
        float s[8][4];
        #pragma unroll
        for (int t = 0; t < 8; t++)
            #pragma unroll
            for (int j = 0; j < 4; j++) s[t][j] = 0.f;

        #pragma unroll
        for (int ks = 0; ks < 8; ks++) {
            #pragma unroll
            for (int t = 0; t < 8; t++) {
                unsigned b0 = __float_as_uint(Ks[8*t + gid][8*ks + qq    ]);
                unsigned b1 = __float_as_uint(Ks[8*t + gid][8*ks + qq + 4]);
                mma_tf32(s[t], qa[ks], b0, b1);
            }
        }

        // ---- online softmax (rows gid -> m0/l0, gid+8 -> m1/l1) ----
        float mx0 = -1e30f, mx1 = -1e30f;
        #pragma unroll
        for (int t = 0; t < 8; t++) {
            mx0 = fmaxf(mx0, fmaxf(s[t][0], s[t][1]));
            mx1 = fmaxf(mx1, fmaxf(s[t][2], s[t][3]));
        }
        mx0 = fmaxf(mx0, __shfl_xor_sync(0xffffffffu, mx0, 1));
        mx0 = fmaxf(mx0, __shfl_xor_sync(0xffffffffu, mx0, 2));
        mx1 = fmaxf(mx1, __shfl_xor_sync(0xffffffffu, mx1, 1));
        mx1 = fmaxf(mx1, __shfl_xor_sync(0xffffffffu, mx1, 2));

        float mn0 = fmaxf(m0, mx0), mn1 = fmaxf(m1, mx1);
        float cr0 = __expf(m0 - mn0), cr1 = __expf(m1 - mn1);
        l0 *= cr0; l1 *= cr1;
        m0 = mn0; m1 = mn1;
        #pragma unroll
        for (int t = 0; t < 8; t++) {
            o[t][0] *= cr0; o[t][1] *= cr0;
            o[t][2] *= cr1; o[t][3] *= cr1;
        }

        // ---- P = exp(S - m), pack to bf16 A-fragments ----
        unsigned pk[8][2];
        #pragma unroll
        for (int t = 0; t < 8; t++) {
            float p0 = __expf(s[t][0] - m0);
            float p1 = __expf(s[t][1] - m0);
            float p2 = __expf(s[t][2] - m1);
            float p3 = __expf(s[t][3] - m1);
            l0 += p0 + p1;
            l1 += p2 + p3;
            pk[t][0] = bf16pack(p0, p1);   // row gid
            pk[t][1] = bf16pack(p2, p3);   // row gid+8
        }

        // ---- O += P * V ----
        #pragma unroll
        for (int ot = 0; ot < 8; ot++) {
            #pragma unroll
            for (int ks = 0; ks < 4; ks++) {
                unsigned vb0 = *(const unsigned*)&Vt[8*ot + gid][16*ks + 2*qq    ];
                unsigned vb1 = *(const unsigned*)&Vt[8*ot + gid][16*ks + 2*qq + 8];
                mma_bf16(o[ot], pk[2*ks][0], pk[2*ks][1],
                                 pk[2*ks+1][0], pk[2*ks+1][1], vb0, vb1);
            }
        }
    }

    // ---- finalize: reduce l across quad, normalize, store ----
    l0 += __shfl_xor_sync(0xffffffffu, l0, 1);
    l0 += __shfl_xor_sync(0xffffffffu, l0, 2);
    l1 += __shfl_xor_sync(0xffffffffu, l1, 1);
    l1 += __shfl_xor_sync(0xffffffffu, l1, 2);
    const float inv0 = 1.f / l0, inv1 = 1.f / l1;

    float* op0 = g_attn + (size_t)(b * NN + n0 + 16*w + gid) * CC + h * DD;
    float* op1 = op0 + (size_t)8 * CC;
    #pragma unroll
    for (int ot = 0; ot < 8; ot++) {
        float2 v0; v0.x = o[ot][0] * inv0; v0.y = o[ot][1] * inv0;
        float2 v1; v1.x = o[ot][2] * inv1; v1.y = o[ot][3] * inv1;
        *(float2*)(op0 + 8*ot + 2*qq) = v0;
        *(float2*)(op1 + 8*ot + 2*qq) = v1;
    }
}

// ---------------------------------------------------------------------------
extern "C" void kernel_launch(void* const* d_in, const int* in_sizes, int n_in,
                              void* d_out, int out_size)
{
    const float* x      = (const float*)d_in[0];
    const float* w_qkv  = (const float*)d_in[1];
    const float* w_proj = (const float*)d_in[2];
    const float* b_proj = (const float*)d_in[3];
    float* out = (float*)d_out;

    float *qkv_ptr, *attn_ptr;
    cudaGetSymbolAddress((void**)&qkv_ptr,  g_qkv);
    cudaGetSymbolAddress((void**)&attn_ptr, g_attn);

    const int M = BB * NN;   // 16384

    // 1) QKV GEMM: [16384,768] x [2304,768]^T -> [16384,2304]
    {
        dim3 grid(F3 / 128, M / 128);
        sgemm_nt<<<grid, 256>>>(x, w_qkv, nullptr, qkv_ptr, M, F3, CC);
    }

    // 2) Attention (tensor cores)
    {
        dim3 grid(NN / QT, HH, BB);
        attn_mma_kernel<<<grid, 128>>>();
    }

    // 3) Proj GEMM + bias: [16384,768] x [768,768]^T -> [16384,768]
    {
        dim3 grid(CC / 128, M / 128);
        sgemm_nt<<<grid, 256>>>(attn_ptr, w_proj, b_proj, out, M, CC, CC);
    }
}

// round 5
// speedup vs baseline: 3.0576x; 1.4289x over previous
#include <cuda_runtime.h>
#include <cuda_bf16.h>
#include <math.h>

#define BB 8
#define NN 2048
#define CC 768
#define HH 12
#define DD 64
#define F3 (3*CC)   // 2304
#define QT 64       // query rows per block
#define KT 64       // keys per tile

// Scratch (static device allocations are the sanctioned no-alloc path)
__device__ float g_qkv[(size_t)BB*NN*F3];   // [B,N,3C]  ~151 MB
__device__ float g_attn[(size_t)BB*NN*CC];  // [B,N,C]   ~50 MB

// ---------------------------------------------------------------------------
// helpers
// ---------------------------------------------------------------------------
__device__ __forceinline__ float tf32r(float x) {
    unsigned u;
    asm("cvt.rna.tf32.f32 %0, %1;" : "=r"(u) : "f"(x));
    return __uint_as_float(u);
}

// D += A(16x8 tf32) * B(8x8 tf32), fp32 accum
__device__ __forceinline__ void mma_tf32(float* c, const unsigned* a,
                                         unsigned b0, unsigned b1) {
    asm volatile(
        "mma.sync.aligned.m16n8k8.row.col.f32.tf32.tf32.f32 "
        "{%0,%1,%2,%3}, {%4,%5,%6,%7}, {%8,%9}, {%0,%1,%2,%3};"
        : "+f"(c[0]), "+f"(c[1]), "+f"(c[2]), "+f"(c[3])
        : "r"(a[0]), "r"(a[1]), "r"(a[2]), "r"(a[3]), "r"(b0), "r"(b1));
}

// ---------------------------------------------------------------------------
// tf32 tensor-core GEMM:  C[m,n] = sum_k A[m,k]*B[n,k] (+ bias[n])
// A: [M,K] row-major, B: [N,K] row-major. 128x128 block, BK=16, 256 thr
// (8 warps, warp tile 32m x 64n). SMEM row-major [row][k] stride 20:
// fragment reads hit banks 20*gid+qq -> all 32 distinct (conflict-free).
// ---------------------------------------------------------------------------
__global__ __launch_bounds__(256)
void gemm_tf32(const float* __restrict__ A, const float* __restrict__ B,
               const float* __restrict__ bias, float* __restrict__ C,
               int M, int N, int K)
{
    __shared__ float As[128][20];
    __shared__ float Bs[128][20];

    const int t    = threadIdx.x;
    const int m0   = blockIdx.y * 128;
    const int n0   = blockIdx.x * 128;
    const int wid  = t >> 5;
    const int lane = t & 31;
    const int gid  = lane >> 2;
    const int qq   = lane & 3;
    const int wm   = (wid & 3) * 32;   // warp m offset
    const int wn   = (wid >> 2) * 64;  // warp n offset

    const int lrow = t >> 1;           // 0..127 (fill row)
    const int lc8  = (t & 1) * 8;      // 0 or 8 (fill k-offset)

    float c[2][8][4];
    #pragma unroll
    for (int i = 0; i < 2; i++)
        #pragma unroll
        for (int j = 0; j < 8; j++)
            #pragma unroll
            for (int v = 0; v < 4; v++) c[i][j][v] = 0.f;

    for (int k0 = 0; k0 < K; k0 += 16) {
        // fill: each thread loads 8 floats (2 float4) of one row of A and B
        {
            const float* ap = A + (size_t)(m0 + lrow) * K + k0 + lc8;
            float4 a0 = *(const float4*)(ap);
            float4 a1 = *(const float4*)(ap + 4);
            As[lrow][lc8+0] = tf32r(a0.x); As[lrow][lc8+1] = tf32r(a0.y);
            As[lrow][lc8+2] = tf32r(a0.z); As[lrow][lc8+3] = tf32r(a0.w);
            As[lrow][lc8+4] = tf32r(a1.x); As[lrow][lc8+5] = tf32r(a1.y);
            As[lrow][lc8+6] = tf32r(a1.z); As[lrow][lc8+7] = tf32r(a1.w);
            const float* bp = B + (size_t)(n0 + lrow) * K + k0 + lc8;
            float4 b0 = *(const float4*)(bp);
            float4 b1 = *(const float4*)(bp + 4);
            Bs[lrow][lc8+0] = tf32r(b0.x); Bs[lrow][lc8+1] = tf32r(b0.y);
            Bs[lrow][lc8+2] = tf32r(b0.z); Bs[lrow][lc8+3] = tf32r(b0.w);
            Bs[lrow][lc8+4] = tf32r(b1.x); Bs[lrow][lc8+5] = tf32r(b1.y);
            Bs[lrow][lc8+6] = tf32r(b1.z); Bs[lrow][lc8+7] = tf32r(b1.w);
        }
        __syncthreads();

        #pragma unroll
        for (int ks = 0; ks < 2; ks++) {
            unsigned a[2][4];
            #pragma unroll
            for (int mt = 0; mt < 2; mt++) {
                int mr = wm + mt * 16;
                a[mt][0] = __float_as_uint(As[mr + gid    ][ks*8 + qq    ]);
                a[mt][1] = __float_as_uint(As[mr + gid + 8][ks*8 + qq    ]);
                a[mt][2] = __float_as_uint(As[mr + gid    ][ks*8 + qq + 4]);
                a[mt][3] = __float_as_uint(As[mr + gid + 8][ks*8 + qq + 4]);
            }
            #pragma unroll
            for (int nt = 0; nt < 8; nt++) {
                unsigned b0 = __float_as_uint(Bs[wn + nt*8 + gid][ks*8 + qq    ]);
                unsigned b1 = __float_as_uint(Bs[wn + nt*8 + gid][ks*8 + qq + 4]);
                mma_tf32(c[0][nt], a[0], b0, b1);
                mma_tf32(c[1][nt], a[1], b0, b1);
            }
        }
        __syncthreads();
    }

    // epilogue
    #pragma unroll
    for (int nt = 0; nt < 8; nt++) {
        int col = n0 + wn + nt * 8 + 2 * qq;
        float b0 = bias ? bias[col]     : 0.f;
        float b1 = bias ? bias[col + 1] : 0.f;
        #pragma unroll
        for (int mt = 0; mt < 2; mt++) {
            int row = m0 + wm + mt * 16 + gid;
            float2 v0; v0.x = c[mt][nt][0] + b0; v0.y = c[mt][nt][1] + b1;
            float2 v1; v1.x = c[mt][nt][2] + b0; v1.y = c[mt][nt][3] + b1;
            *(float2*)(C + (size_t)row * N + col)       = v0;
            *(float2*)(C + (size_t)(row + 8) * N + col) = v1;
        }
    }
}

// ---------------------------------------------------------------------------
// Flash attention on tensor cores, all-tf32 MMA path.
// Block = (64 q-rows, head h, batch b), 128 threads (4 warps).
// Warp w owns S/O strip of rows [16w, 16w+16).
// QK^T: tf32 mma m16n8k8 (scale folded into Q).
// P*V : tf32 mma m16n8k8; P A-fragments built from S accumulators via
//       intra-quad shuffles; V kept [key][d] fp32 (stride 72 -> banks
//       8*qq+gid, conflict-free B-fragments).
// SMEM: Q buffer (dead after fragment extraction) is unioned with K+V.
// ---------------------------------------------------------------------------
__global__ __launch_bounds__(128)
void attn_mma_kernel()
{
    __shared__ float pool[KT*68 + KT*72];    // Ks[64][68] + Vs[64][72]; Qs aliases
    float (*Qs)[68] = (float(*)[68])pool;
    float (*Ks)[68] = (float(*)[68])pool;
    float (*Vs)[72] = (float(*)[72])(pool + KT*68);

    const int b  = blockIdx.z;
    const int h  = blockIdx.y;
    const int n0 = blockIdx.x * QT;
    const int tid  = threadIdx.x;
    const int w    = tid >> 5;
    const int lane = tid & 31;
    const int gid  = lane >> 2;   // 0..7
    const int qq   = lane & 3;    // 0..3

    const size_t base_bn = (size_t)(b * NN) * F3;

    // ---- load Q tile (scaled by D^-0.5, tf32-rounded) ----
    #pragma unroll
    for (int r = 0; r < 8; r++) {
        int idx = r * 128 + tid;        // 0..1023 float4s
        int row = idx >> 4;
        int c4  = idx & 15;
        const float* gp = g_qkv + base_bn + (size_t)(n0 + row) * F3 + h * DD + c4 * 4;
        float4 v = *(const float4*)gp;
        Qs[row][c4*4+0] = tf32r(v.x * 0.125f);
        Qs[row][c4*4+1] = tf32r(v.y * 0.125f);
        Qs[row][c4*4+2] = tf32r(v.z * 0.125f);
        Qs[row][c4*4+3] = tf32r(v.w * 0.125f);
    }
    __syncthreads();

    // ---- Q A-fragments (registers for whole kernel) ----
    unsigned qa[8][4];
    #pragma unroll
    for (int ks = 0; ks < 8; ks++) {
        qa[ks][0] = __float_as_uint(Qs[16*w + gid    ][8*ks + qq    ]);
        qa[ks][1] = __float_as_uint(Qs[16*w + gid + 8][8*ks + qq    ]);
        qa[ks][2] = __float_as_uint(Qs[16*w + gid    ][8*ks + qq + 4]);
        qa[ks][3] = __float_as_uint(Qs[16*w + gid + 8][8*ks + qq + 4]);
    }
    __syncthreads();   // Qs consumed; pool may be reused as Ks/Vs

    float o[8][4];
    #pragma unroll
    for (int t = 0; t < 8; t++)
        #pragma unroll
        for (int j = 0; j < 4; j++) o[t][j] = 0.f;
    float m0 = -1e30f, m1 = -1e30f, l0 = 0.f, l1 = 0.f;

    for (int kt = 0; kt < NN / KT; kt++) {
        // ---- load K tile and V tile (both tf32-rounded fp32) ----
        #pragma unroll
        for (int r = 0; r < 8; r++) {
            int idx = r * 128 + tid;
            int row = idx >> 4;
            int c4  = idx & 15;
            const float* kp = g_qkv + base_bn + (size_t)(kt * KT + row) * F3
                              + CC + h * DD + c4 * 4;
            float4 kv = *(const float4*)kp;
            Ks[row][c4*4+0] = tf32r(kv.x);
            Ks[row][c4*4+1] = tf32r(kv.y);
            Ks[row][c4*4+2] = tf32r(kv.z);
            Ks[row][c4*4+3] = tf32r(kv.w);
            float4 vv = *(const float4*)(kp + CC);
            Vs[row][c4*4+0] = tf32r(vv.x);
            Vs[row][c4*4+1] = tf32r(vv.y);
            Vs[row][c4*4+2] = tf32r(vv.z);
            Vs[row][c4*4+3] = tf32r(vv.w);
        }
        __syncthreads();

        // ---- S = Q * K^T  (warp strip 16x64) ----
        float s[8][4];
        #pragma unroll
        for (int t = 0; t < 8; t++)
            #pragma unroll
            for (int j = 0; j < 4; j++) s[t][j] = 0.f;

        #pragma unroll
        for (int ks = 0; ks < 8; ks++) {
            #pragma unroll
            for (int t = 0; t < 8; t++) {
                unsigned b0 = __float_as_uint(Ks[8*t + gid][8*ks + qq    ]);
                unsigned b1 = __float_as_uint(Ks[8*t + gid][8*ks + qq + 4]);
                mma_tf32(s[t], qa[ks], b0, b1);
            }
        }

        // ---- online softmax (rows gid -> m0/l0, gid+8 -> m1/l1) ----
        float mx0 = -1e30f, mx1 = -1e30f;
        #pragma unroll
        for (int t = 0; t < 8; t++) {
            mx0 = fmaxf(mx0, fmaxf(s[t][0], s[t][1]));
            mx1 = fmaxf(mx1, fmaxf(s[t][2], s[t][3]));
        }
        mx0 = fmaxf(mx0, __shfl_xor_sync(0xffffffffu, mx0, 1));
        mx0 = fmaxf(mx0, __shfl_xor_sync(0xffffffffu, mx0, 2));
        mx1 = fmaxf(mx1, __shfl_xor_sync(0xffffffffu, mx1, 1));
        mx1 = fmaxf(mx1, __shfl_xor_sync(0xffffffffu, mx1, 2));

        float mn0 = fmaxf(m0, mx0), mn1 = fmaxf(m1, mx1);
        float cr0 = __expf(m0 - mn0), cr1 = __expf(m1 - mn1);
        l0 *= cr0; l1 *= cr1;
        m0 = mn0; m1 = mn1;
        #pragma unroll
        for (int t = 0; t < 8; t++) {
            o[t][0] *= cr0; o[t][1] *= cr0;
            o[t][2] *= cr1; o[t][3] *= cr1;
        }

        // ---- P = tf32(exp(S - m)) kept in s[][]; l sums the rounded P ----
        #pragma unroll
        for (int t = 0; t < 8; t++) {
            float p0 = tf32r(__expf(s[t][0] - m0));
            float p1 = tf32r(__expf(s[t][1] - m0));
            float p2 = tf32r(__expf(s[t][2] - m1));
            float p3 = tf32r(__expf(s[t][3] - m1));
            l0 += p0 + p1;
            l1 += p2 + p3;
            s[t][0] = p0; s[t][1] = p1; s[t][2] = p2; s[t][3] = p3;
        }

        // ---- O += P * V  (tf32 mma; A-frags via intra-quad shuffles) ----
        #pragma unroll
        for (int ks = 0; ks < 8; ks++) {
            // need P[gid][qq], P[gid+8][qq], P[gid][qq+4], P[gid+8][qq+4]
            // holder of P[gid][c]: lane (gid, c>>1), component (c&1) [+2 for gid+8]
            int srcA = (lane & ~3) | (qq >> 1);   // for col qq
            int srcB = srcA + 2;                  // for col qq+4
            float u0 = __shfl_sync(0xffffffffu, s[ks][0], srcA);
            float u1 = __shfl_sync(0xffffffffu, s[ks][1], srcA);
            float u2 = __shfl_sync(0xffffffffu, s[ks][2], srcA);
            float u3 = __shfl_sync(0xffffffffu, s[ks][3], srcA);
            float w0 = __shfl_sync(0xffffffffu, s[ks][0], srcB);
            float w1 = __shfl_sync(0xffffffffu, s[ks][1], srcB);
            float w2 = __shfl_sync(0xffffffffu, s[ks][2], srcB);
            float w3 = __shfl_sync(0xffffffffu, s[ks][3], srcB);
            bool odd = (qq & 1);
            unsigned pa[4];
            pa[0] = __float_as_uint(odd ? u1 : u0);
            pa[1] = __float_as_uint(odd ? u3 : u2);
            pa[2] = __float_as_uint(odd ? w1 : w0);
            pa[3] = __float_as_uint(odd ? w3 : w2);

            #pragma unroll
            for (int ot = 0; ot < 8; ot++) {
                unsigned vb0 = __float_as_uint(Vs[8*ks + qq    ][8*ot + gid]);
                unsigned vb1 = __float_as_uint(Vs[8*ks + qq + 4][8*ot + gid]);
                mma_tf32(o[ot], pa, vb0, vb1);
            }
        }
        __syncthreads();   // tile fully consumed before reload
    }

    // ---- finalize: reduce l across quad, normalize, store ----
    l0 += __shfl_xor_sync(0xffffffffu, l0, 1);
    l0 += __shfl_xor_sync(0xffffffffu, l0, 2);
    l1 += __shfl_xor_sync(0xffffffffu, l1, 1);
    l1 += __shfl_xor_sync(0xffffffffu, l1, 2);
    const float inv0 = 1.f / l0, inv1 = 1.f / l1;

    float* op0 = g_attn + (size_t)(b * NN + n0 + 16*w + gid) * CC + h * DD;
    float* op1 = op0 + (size_t)8 * CC;
    #pragma unroll
    for (int ot = 0; ot < 8; ot++) {
        float2 v0; v0.x = o[ot][0] * inv0; v0.y = o[ot][1] * inv0;
        float2 v1; v1.x = o[ot][2] * inv1; v1.y = o[ot][3] * inv1;
        *(float2*)(op0 + 8*ot + 2*qq) = v0;
        *(float2*)(op1 + 8*ot + 2*qq) = v1;
    }
}

// ---------------------------------------------------------------------------
extern "C" void kernel_launch(void* const* d_in, const int* in_sizes, int n_in,
                              void* d_out, int out_size)
{
    const float* x      = (const float*)d_in[0];
    const float* w_qkv  = (const float*)d_in[1];
    const float* w_proj = (const float*)d_in[2];
    const float* b_proj = (const float*)d_in[3];
    float* out = (float*)d_out;

    float *qkv_ptr, *attn_ptr;
    cudaGetSymbolAddress((void**)&qkv_ptr,  g_qkv);
    cudaGetSymbolAddress((void**)&attn_ptr, g_attn);

    const int M = BB * NN;   // 16384

    // 1) QKV GEMM: [16384,768] x [2304,768]^T -> [16384,2304]
    {
        dim3 grid(F3 / 128, M / 128);
        gemm_tf32<<<grid, 256>>>(x, w_qkv, nullptr, qkv_ptr, M, F3, CC);
    }

    // 2) Attention (tensor cores)
    {
        dim3 grid(NN / QT, HH, BB);
        attn_mma_kernel<<<grid, 128>>>();
    }

    // 3) Proj GEMM + bias: [16384,768] x [768,768]^T -> [16384,768]
    {
        dim3 grid(CC / 128, M / 128);
        gemm_tf32<<<grid, 256>>>(attn_ptr, w_proj, b_proj, out, M, CC, CC);
    }
}

// round 6
// speedup vs baseline: 3.3314x; 1.0896x over previous
#include <cuda_runtime.h>
#include <cuda_bf16.h>
#include <math.h>

#define BB 8
#define NN 2048
#define CC 768
#define HH 12
#define DD 64
#define F3 (3*CC)   // 2304
#define QT 128      // query rows per block
#define KT 64       // keys per tile

// Scratch (static device allocations are the sanctioned no-alloc path)
__device__ float g_qkv[(size_t)BB*NN*F3];   // [B,N,3C]  ~151 MB
__device__ float g_attn[(size_t)BB*NN*CC];  // [B,N,C]   ~50 MB

// ---------------------------------------------------------------------------
// helpers
// ---------------------------------------------------------------------------
__device__ __forceinline__ float tf32r(float x) {
    unsigned u;
    asm("cvt.rna.tf32.f32 %0, %1;" : "=r"(u) : "f"(x));
    return __uint_as_float(u);
}

// D += A(16x8 tf32) * B(8x8 tf32), fp32 accum
__device__ __forceinline__ void mma_tf32(float* c, const unsigned* a,
                                         unsigned b0, unsigned b1) {
    asm volatile(
        "mma.sync.aligned.m16n8k8.row.col.f32.tf32.tf32.f32 "
        "{%0,%1,%2,%3}, {%4,%5,%6,%7}, {%8,%9}, {%0,%1,%2,%3};"
        : "+f"(c[0]), "+f"(c[1]), "+f"(c[2]), "+f"(c[3])
        : "r"(a[0]), "r"(a[1]), "r"(a[2]), "r"(a[3]), "r"(b0), "r"(b1));
}

// ---------------------------------------------------------------------------
// tf32 tensor-core GEMM with register-prefetch software pipeline.
// C[m,n] = sum_k A[m,k]*B[n,k] (+ bias[n]); A:[M,K], B:[N,K] row-major.
// 128x128 block, BK=16, 256 thr (8 warps, warp tile 32m x 64n).
// SMEM [row][k] stride 20 -> fragment reads conflict-free.
// Loop: store(prefetch regs->smem,cvt); sync; LDG next slab; compute; sync.
// ---------------------------------------------------------------------------
__global__ __launch_bounds__(256)
void gemm_tf32(const float* __restrict__ A, const float* __restrict__ B,
               const float* __restrict__ bias, float* __restrict__ C,
               int M, int N, int K)
{
    __shared__ float As[128][20];
    __shared__ float Bs[128][20];

    const int t    = threadIdx.x;
    const int m0   = blockIdx.y * 128;
    const int n0   = blockIdx.x * 128;
    const int wid  = t >> 5;
    const int lane = t & 31;
    const int gid  = lane >> 2;
    const int qq   = lane & 3;
    const int wm   = (wid & 3) * 32;   // warp m offset
    const int wn   = (wid >> 2) * 64;  // warp n offset

    const int lrow = t >> 1;           // 0..127 (fill row)
    const int lc8  = (t & 1) * 8;      // 0 or 8 (fill k-offset)

    const float* aRow = A + (size_t)(m0 + lrow) * K + lc8;
    const float* bRow = B + (size_t)(n0 + lrow) * K + lc8;

    float c[2][8][4];
    #pragma unroll
    for (int i = 0; i < 2; i++)
        #pragma unroll
        for (int j = 0; j < 8; j++)
            #pragma unroll
            for (int v = 0; v < 4; v++) c[i][j][v] = 0.f;

    // prefetch slab k0=0
    float4 pa0 = *(const float4*)(aRow);
    float4 pa1 = *(const float4*)(aRow + 4);
    float4 pb0 = *(const float4*)(bRow);
    float4 pb1 = *(const float4*)(bRow + 4);

    for (int k0 = 0; k0 < K; k0 += 16) {
        // commit prefetched slab to SMEM (tf32-rounded)
        As[lrow][lc8+0] = tf32r(pa0.x); As[lrow][lc8+1] = tf32r(pa0.y);
        As[lrow][lc8+2] = tf32r(pa0.z); As[lrow][lc8+3] = tf32r(pa0.w);
        As[lrow][lc8+4] = tf32r(pa1.x); As[lrow][lc8+5] = tf32r(pa1.y);
        As[lrow][lc8+6] = tf32r(pa1.z); As[lrow][lc8+7] = tf32r(pa1.w);
        Bs[lrow][lc8+0] = tf32r(pb0.x); Bs[lrow][lc8+1] = tf32r(pb0.y);
        Bs[lrow][lc8+2] = tf32r(pb0.z); Bs[lrow][lc8+3] = tf32r(pb0.w);
        Bs[lrow][lc8+4] = tf32r(pb1.x); Bs[lrow][lc8+5] = tf32r(pb1.y);
        Bs[lrow][lc8+6] = tf32r(pb1.z); Bs[lrow][lc8+7] = tf32r(pb1.w);
        __syncthreads();

        // issue LDG for next slab (latency hides behind the mma block)
        if (k0 + 16 < K) {
            pa0 = *(const float4*)(aRow + k0 + 16);
            pa1 = *(const float4*)(aRow + k0 + 20);
            pb0 = *(const float4*)(bRow + k0 + 16);
            pb1 = *(const float4*)(bRow + k0 + 20);
        }

        #pragma unroll
        for (int ks = 0; ks < 2; ks++) {
            unsigned a[2][4];
            #pragma unroll
            for (int mt = 0; mt < 2; mt++) {
                int mr = wm + mt * 16;
                a[mt][0] = __float_as_uint(As[mr + gid    ][ks*8 + qq    ]);
                a[mt][1] = __float_as_uint(As[mr + gid + 8][ks*8 + qq    ]);
                a[mt][2] = __float_as_uint(As[mr + gid    ][ks*8 + qq + 4]);
                a[mt][3] = __float_as_uint(As[mr + gid + 8][ks*8 + qq + 4]);
            }
            #pragma unroll
            for (int nt = 0; nt < 8; nt++) {
                unsigned b0 = __float_as_uint(Bs[wn + nt*8 + gid][ks*8 + qq    ]);
                unsigned b1 = __float_as_uint(Bs[wn + nt*8 + gid][ks*8 + qq + 4]);
                mma_tf32(c[0][nt], a[0], b0, b1);
                mma_tf32(c[1][nt], a[1], b0, b1);
            }
        }
        __syncthreads();
    }

    // epilogue
    #pragma unroll
    for (int nt = 0; nt < 8; nt++) {
        int col = n0 + wn + nt * 8 + 2 * qq;
        float b0 = bias ? bias[col]     : 0.f;
        float b1 = bias ? bias[col + 1] : 0.f;
        #pragma unroll
        for (int mt = 0; mt < 2; mt++) {
            int row = m0 + wm + mt * 16 + gid;
            float2 v0; v0.x = c[mt][nt][0] + b0; v0.y = c[mt][nt][1] + b1;
            float2 v1; v1.x = c[mt][nt][2] + b0; v1.y = c[mt][nt][3] + b1;
            *(float2*)(C + (size_t)row * N + col)       = v0;
            *(float2*)(C + (size_t)(row + 8) * N + col) = v1;
        }
    }
}

// ---------------------------------------------------------------------------
// Flash attention, all-tf32 MMA, register-prefetch pipelined.
// Block = (128 q-rows, head h, batch b), 256 threads (8 warps).
// Warp w owns S/O strip rows [16w, 16w+16).
// QK^T: tf32 mma m16n8k8 (scale folded into Q).
// P*V : tf32 mma m16n8k8; P A-frags from S accumulators via quad shuffles;
//       V kept [key][d] (stride 72 -> conflict-free B-frags).
// K/V tile for step kt+1 is LDG'd into registers while step kt computes.
// ---------------------------------------------------------------------------
__global__ __launch_bounds__(256)
void attn_mma_kernel()
{
    __shared__ float pool[KT*68 + KT*72];    // Ks[64][68] + Vs[64][72]
    float (*Qs)[68] = (float(*)[68])pool;    // Qs[128][68] aliases (dead after prologue)
    float (*Ks)[68] = (float(*)[68])pool;
    float (*Vs)[72] = (float(*)[72])(pool + KT*68);

    const int b  = blockIdx.z;
    const int h  = blockIdx.y;
    const int n0 = blockIdx.x * QT;
    const int tid  = threadIdx.x;
    const int w    = tid >> 5;    // 0..7
    const int lane = tid & 31;
    const int gid  = lane >> 2;   // 0..7
    const int qq   = lane & 3;    // 0..3

    const size_t base_bn = (size_t)(b * NN) * F3;
    const float* kBase = g_qkv + base_bn + CC + h * DD;   // K rows; V at +CC

    // ---- load Q tile [128][64] (scaled, tf32-rounded) ----
    #pragma unroll
    for (int r = 0; r < 8; r++) {
        int idx = r * 256 + tid;        // 0..2047 float4s
        int row = idx >> 4;
        int c4  = idx & 15;
        const float* gp = g_qkv + base_bn + (size_t)(n0 + row) * F3 + h * DD + c4 * 4;
        float4 v = *(const float4*)gp;
        Qs[row][c4*4+0] = tf32r(v.x * 0.125f);
        Qs[row][c4*4+1] = tf32r(v.y * 0.125f);
        Qs[row][c4*4+2] = tf32r(v.z * 0.125f);
        Qs[row][c4*4+3] = tf32r(v.w * 0.125f);
    }
    __syncthreads();

    // ---- Q A-fragments (registers for whole kernel) ----
    unsigned qa[8][4];
    #pragma unroll
    for (int ks = 0; ks < 8; ks++) {
        qa[ks][0] = __float_as_uint(Qs[16*w + gid    ][8*ks + qq    ]);
        qa[ks][1] = __float_as_uint(Qs[16*w + gid + 8][8*ks + qq    ]);
        qa[ks][2] = __float_as_uint(Qs[16*w + gid    ][8*ks + qq + 4]);
        qa[ks][3] = __float_as_uint(Qs[16*w + gid + 8][8*ks + qq + 4]);
    }
    __syncthreads();   // Qs consumed; pool becomes Ks/Vs

    float o[8][4];
    #pragma unroll
    for (int t = 0; t < 8; t++)
        #pragma unroll
        for (int j = 0; j < 4; j++) o[t][j] = 0.f;
    float m0 = -1e30f, m1 = -1e30f, l0 = 0.f, l1 = 0.f;

    // ---- prefetch tile 0 (K: pf[0..3], V: pf[4..7]) ----
    float4 pf[8];
    #pragma unroll
    for (int r = 0; r < 4; r++) {
        int idx = r * 256 + tid;        // 0..1023
        int row = idx >> 4, c4 = idx & 15;
        pf[r]     = *(const float4*)(kBase + (size_t)row * F3 + c4 * 4);
        pf[r + 4] = *(const float4*)(kBase + (size_t)row * F3 + CC + c4 * 4);
    }

    for (int kt = 0; kt < NN / KT; kt++) {
        // ---- commit prefetched K/V to SMEM (tf32-rounded) ----
        #pragma unroll
        for (int r = 0; r < 4; r++) {
            int idx = r * 256 + tid;
            int row = idx >> 4, c4 = idx & 15;
            Ks[row][c4*4+0] = tf32r(pf[r].x);
            Ks[row][c4*4+1] = tf32r(pf[r].y);
            Ks[row][c4*4+2] = tf32r(pf[r].z);
            Ks[row][c4*4+3] = tf32r(pf[r].w);
            Vs[row][c4*4+0] = tf32r(pf[r+4].x);
            Vs[row][c4*4+1] = tf32r(pf[r+4].y);
            Vs[row][c4*4+2] = tf32r(pf[r+4].z);
            Vs[row][c4*4+3] = tf32r(pf[r+4].w);
        }
        __syncthreads();

        // ---- issue LDG for next tile (hidden behind compute) ----
        if (kt + 1 < NN / KT) {
            const float* kb = kBase + (size_t)((kt + 1) * KT) * F3;
            #pragma unroll
            for (int r = 0; r < 4; r++) {
                int idx = r * 256 + tid;
                int row = idx >> 4, c4 = idx & 15;
                pf[r]     = *(const float4*)(kb + (size_t)row * F3 + c4 * 4);
                pf[r + 4] = *(const float4*)(kb + (size_t)row * F3 + CC + c4 * 4);
            }
        }

        // ---- S = Q * K^T  (warp strip 16x64) ----
        float s[8][4];
        #pragma unroll
        for (int t = 0; t < 8; t++)
            #pragma unroll
            for (int j = 0; j < 4; j++) s[t][j] = 0.f;

        #pragma unroll
        for (int ks = 0; ks < 8; ks++) {
            #pragma unroll
            for (int t = 0; t < 8; t++) {
                unsigned b0 = __float_as_uint(Ks[8*t + gid][8*ks + qq    ]);
                unsigned b1 = __float_as_uint(Ks[8*t + gid][8*ks + qq + 4]);
                mma_tf32(s[t], qa[ks], b0, b1);
            }
        }

        // ---- online softmax (rows gid -> m0/l0, gid+8 -> m1/l1) ----
        float mx0 = -1e30f, mx1 = -1e30f;
        #pragma unroll
        for (int t = 0; t < 8; t++) {
            mx0 = fmaxf(mx0, fmaxf(s[t][0], s[t][1]));
            mx1 = fmaxf(mx1, fmaxf(s[t][2], s[t][3]));
        }
        mx0 = fmaxf(mx0, __shfl_xor_sync(0xffffffffu, mx0, 1));
        mx0 = fmaxf(mx0, __shfl_xor_sync(0xffffffffu, mx0, 2));
        mx1 = fmaxf(mx1, __shfl_xor_sync(0xffffffffu, mx1, 1));
        mx1 = fmaxf(mx1, __shfl_xor_sync(0xffffffffu, mx1, 2));

        float mn0 = fmaxf(m0, mx0), mn1 = fmaxf(m1, mx1);
        float cr0 = __expf(m0 - mn0), cr1 = __expf(m1 - mn1);
        l0 *= cr0; l1 *= cr1;
        m0 = mn0; m1 = mn1;
        #pragma unroll
        for (int t = 0; t < 8; t++) {
            o[t][0] *= cr0; o[t][1] *= cr0;
            o[t][2] *= cr1; o[t][3] *= cr1;
        }

        // ---- P = tf32(exp(S - m)); l sums the rounded P ----
        #pragma unroll
        for (int t = 0; t < 8; t++) {
            float p0 = tf32r(__expf(s[t][0] - m0));
            float p1 = tf32r(__expf(s[t][1] - m0));
            float p2 = tf32r(__expf(s[t][2] - m1));
            float p3 = tf32r(__expf(s[t][3] - m1));
            l0 += p0 + p1;
            l1 += p2 + p3;
            s[t][0] = p0; s[t][1] = p1; s[t][2] = p2; s[t][3] = p3;
        }

        // ---- O += P * V  (A-frags via intra-quad shuffles) ----
        #pragma unroll
        for (int ks = 0; ks < 8; ks++) {
            int srcA = (lane & ~3) | (qq >> 1);   // holder of col qq
            int srcB = srcA + 2;                  // holder of col qq+4
            float u0 = __shfl_sync(0xffffffffu, s[ks][0], srcA);
            float u1 = __shfl_sync(0xffffffffu, s[ks][1], srcA);
            float u2 = __shfl_sync(0xffffffffu, s[ks][2], srcA);
            float u3 = __shfl_sync(0xffffffffu, s[ks][3], srcA);
            float w0 = __shfl_sync(0xffffffffu, s[ks][0], srcB);
            float w1 = __shfl_sync(0xffffffffu, s[ks][1], srcB);
            float w2 = __shfl_sync(0xffffffffu, s[ks][2], srcB);
            float w3 = __shfl_sync(0xffffffffu, s[ks][3], srcB);
            bool odd = (qq & 1);
            unsigned pa[4];
            pa[0] = __float_as_uint(odd ? u1 : u0);
            pa[1] = __float_as_uint(odd ? u3 : u2);
            pa[2] = __float_as_uint(odd ? w1 : w0);
            pa[3] = __float_as_uint(odd ? w3 : w2);

            #pragma unroll
            for (int ot = 0; ot < 8; ot++) {
                unsigned vb0 = __float_as_uint(Vs[8*ks + qq    ][8*ot + gid]);
                unsigned vb1 = __float_as_uint(Vs[8*ks + qq + 4][8*ot + gid]);
                mma_tf32(o[ot], pa, vb0, vb1);
            }
        }
        __syncthreads();   // tile consumed before next commit
    }

    // ---- finalize: reduce l across quad, normalize, store ----
    l0 += __shfl_xor_sync(0xffffffffu, l0, 1);
    l0 += __shfl_xor_sync(0xffffffffu, l0, 2);
    l1 += __shfl_xor_sync(0xffffffffu, l1, 1);
    l1 += __shfl_xor_sync(0xffffffffu, l1, 2);
    const float inv0 = 1.f / l0, inv1 = 1.f / l1;

    float* op0 = g_attn + (size_t)(b * NN + n0 + 16*w + gid) * CC + h * DD;
    float* op1 = op0 + (size_t)8 * CC;
    #pragma unroll
    for (int ot = 0; ot < 8; ot++) {
        float2 v0; v0.x = o[ot][0] * inv0; v0.y = o[ot][1] * inv0;
        float2 v1; v1.x = o[ot][2] * inv1; v1.y = o[ot][3] * inv1;
        *(float2*)(op0 + 8*ot + 2*qq) = v0;
        *(float2*)(op1 + 8*ot + 2*qq) = v1;
    }
}

// ---------------------------------------------------------------------------
extern "C" void kernel_launch(void* const* d_in, const int* in_sizes, int n_in,
                              void* d_out, int out_size)
{
    const float* x      = (const float*)d_in[0];
    const float* w_qkv  = (const float*)d_in[1];
    const float* w_proj = (const float*)d_in[2];
    const float* b_proj = (const float*)d_in[3];
    float* out = (float*)d_out;

    float *qkv_ptr, *attn_ptr;
    cudaGetSymbolAddress((void**)&qkv_ptr,  g_qkv);
    cudaGetSymbolAddress((void**)&attn_ptr, g_attn);

    const int M = BB * NN;   // 16384

    // 1) QKV GEMM: [16384,768] x [2304,768]^T -> [16384,2304]
    {
        dim3 grid(F3 / 128, M / 128);
        gemm_tf32<<<grid, 256>>>(x, w_qkv, nullptr, qkv_ptr, M, F3, CC);
    }

    // 2) Attention (tensor cores)
    {
        dim3 grid(NN / QT, HH, BB);
        attn_mma_kernel<<<grid, 256>>>();
    }

    // 3) Proj GEMM + bias: [16384,768] x [768,768]^T -> [16384,768]
    {
        dim3 grid(CC / 128, M / 128);
        gemm_tf32<<<grid, 256>>>(attn_ptr, w_proj, b_proj, out, M, CC, CC);
    }
}